// round 16
// baseline (speedup 1.0000x reference)
#include <cuda_runtime.h>
#include <math.h>

typedef unsigned long long ull;

// Problem constants
#define BB 4
#define NN 2048
#define DD 128
#define HH 4
#define DH 32
#define DOUT 256
#define MTOT (BB*NN)          // 8192
#define SCALE 0.088388347648318440550f  // 1/sqrt(128)
#define HALF_SCALE 0.044194173824159220275f // SCALE/2
#define NSPLIT 2
#define KEYS_PER_SPLIT (NN/NSPLIT)
#define NW 10                  // number of pre-split weight matrices

// ---------------- scratch (device globals; no allocations allowed) ----------
__device__ float g_Q[MTOT*DD];
__device__ float g_K[MTOT*DD];
__device__ float g_V[MTOT*DD];
__device__ float g_O[NSPLIT*MTOT*DD];   // split partial attention outputs
__device__ float g_X[MTOT*DD];
__device__ float g_P[BB*DD];
__device__ float2 g_Wsp[NW*DD*DD];      // pre-split weights (hi, lo)

// ---------------- tf32 helpers ----------------------------------------------
__device__ __forceinline__ unsigned f2tf(float f) {
    unsigned u; asm("cvt.rna.tf32.f32 %0, %1;" : "=r"(u) : "f"(f)); return u;
}
__device__ __forceinline__ float tf2f(unsigned u) { return __uint_as_float(u); }

__device__ __forceinline__ void mma_tf32(float c[4], const unsigned a[4],
                                         unsigned b0, unsigned b1) {
    asm volatile(
        "mma.sync.aligned.m16n8k8.row.col.f32.tf32.tf32.f32 "
        "{%0,%1,%2,%3}, {%4,%5,%6,%7}, {%8,%9}, {%0,%1,%2,%3};"
        : "+f"(c[0]), "+f"(c[1]), "+f"(c[2]), "+f"(c[3])
        : "r"(a[0]), "r"(a[1]), "r"(a[2]), "r"(a[3]), "r"(b0), "r"(b1));
}

// sigmoid via MUFU.TANH: sigm(dot*SCALE) = 0.5*tanh(dot*SCALE/2) + 0.5
__device__ __forceinline__ float sigm(float dot) {
    float t;
    asm("tanh.approx.f32 %0, %1;" : "=f"(t) : "f"(dot * HALF_SCALE));
    return fmaf(0.5f, t, 0.5f);
}

// ---------------- fused weight pre-split (all 10 matrices, one launch) -------
struct WPtrs { const float* w[NW]; };

__global__ void wsplit_all_kernel(WPtrs p, float2* __restrict__ out)
{
    int i = blockIdx.x * 256 + threadIdx.x;     // grid sized exactly NW*DD*DD
    int slot = i >> 14;                          // DD*DD = 16384 = 2^14
    int off  = i & 16383;
    float w = p.w[slot][off];
    float hi = tf2f(f2tf(w));
    float lo = tf2f(f2tf(w - hi));
    out[i] = make_float2(hi, lo);
}

// ---------------- tf32 mma flash sigmoid-attention (ROUND-8 PROVEN) ---------
// Per CTA: (b, h, split, qtile of 128 rows). 4 warps, each warp: 32 q-rows.
// Key tiles of 64. O_part[split] = (split==0 ? Qh : 0) + sigmoid(QK^T*s)V.
// NSPLIT=2: 512 CTAs = one clean wave at occupancy 4; halves partial-O DRAM
// traffic vs NSPLIT=4 (the mode-2 GEMM was measured DRAM-bound on it).
// IMPORTANT: all tf32 operands are rounded with cvt.rna (round-to-nearest).
// Relying on the tensor core's implicit truncation introduces a SYSTEMATIC
// bias on the (strictly positive) attention weights that accumulates over
// the 2048-key reduction — measured 22x rel_err blowup. Do not remove.
#define SK_F   (64*40)        // 2560 floats
#define SV_F   (32*72)        // 2304 floats
#define SA_F   (32*72)        // per warp
#define SMEM_F (SK_F + SV_F + 4*SA_F)   // 14080 floats = 55 KB

__global__ __launch_bounds__(128, 4) void attn_mma_kernel(
    const float* __restrict__ Q, const float* __restrict__ K,
    const float* __restrict__ V, float* __restrict__ O)
{
    extern __shared__ float smem[];
    float* sK   = smem;
    float* sVhi = smem + SK_F;
    float* sA   = sVhi + SV_F;

    const int w    = threadIdx.x >> 5;
    const int lane = threadIdx.x & 31;
    const int g    = lane >> 2;
    const int tig  = lane & 3;

    const int qt    = blockIdx.x;
    const int h     = blockIdx.y & 3;
    const int split = blockIdx.y >> 2;
    const int b     = blockIdx.z;

    float* Aw = sA + w * SA_F;

    const float* Qw = Q + ((size_t)b * NN + qt * 128 + w * 32) * DD + h * DH;
    const float* Kg = K + (size_t)b * NN * DD + h * DH + (size_t)split * KEYS_PER_SPLIT * DD;
    const float* Vg = V + (size_t)b * NN * DD + h * DH + (size_t)split * KEYS_PER_SPLIT * DD;
    float* Og = O + (size_t)split * MTOT * DD + ((size_t)b * NN + qt * 128 + w * 32) * DD + h * DH;

    // Q fragments (tf32, rounded once)
    unsigned qa[2][4][4];
#pragma unroll
    for (int mt = 0; mt < 2; mt++)
#pragma unroll
        for (int ks = 0; ks < 4; ks++) {
            qa[mt][ks][0] = f2tf(Qw[(mt*16 + g    ) * DD + ks*8 + tig    ]);
            qa[mt][ks][1] = f2tf(Qw[(mt*16 + g + 8) * DD + ks*8 + tig    ]);
            qa[mt][ks][2] = f2tf(Qw[(mt*16 + g    ) * DD + ks*8 + tig + 4]);
            qa[mt][ks][3] = f2tf(Qw[(mt*16 + g + 8) * DD + ks*8 + tig + 4]);
        }

    // O accumulators; residual Qh in split 0
    float oc[2][4][4];
#pragma unroll
    for (int mt = 0; mt < 2; mt++)
#pragma unroll
        for (int nb = 0; nb < 4; nb++) {
            if (split == 0) {
                oc[mt][nb][0] = Qw[(mt*16 + g    ) * DD + nb*8 + 2*tig    ];
                oc[mt][nb][1] = Qw[(mt*16 + g    ) * DD + nb*8 + 2*tig + 1];
                oc[mt][nb][2] = Qw[(mt*16 + g + 8) * DD + nb*8 + 2*tig    ];
                oc[mt][nb][3] = Qw[(mt*16 + g + 8) * DD + nb*8 + 2*tig + 1];
            } else {
                oc[mt][nb][0] = oc[mt][nb][1] = oc[mt][nb][2] = oc[mt][nb][3] = 0.f;
            }
        }

    const int c0p = (tig >> 1) + ((tig & 1) << 2);  // permuted col: {0,4,1,5}

    for (int kt = 0; kt < KEYS_PER_SPLIT / 64; kt++) {
        // ---- load K/V tile (64 keys x 32 dims), tf32-rounded (rna) ----
#pragma unroll
        for (int r = 0; r < 4; r++) {
            int gi  = r * 128 + threadIdx.x;
            int key = gi >> 3;
            int j   = gi & 7;
            const float4 k4 = *reinterpret_cast<const float4*>(
                Kg + (size_t)(kt * 64 + key) * DD + j * 4);
            const float4 v4 = *reinterpret_cast<const float4*>(
                Vg + (size_t)(kt * 64 + key) * DD + j * 4);
            {
                int base = key * 40 + (j >> 1) * 8 + (j & 1);
                sK[base + 0] = tf2f(f2tf(k4.x));
                sK[base + 2] = tf2f(f2tf(k4.y));
                sK[base + 4] = tf2f(f2tf(k4.z));
                sK[base + 6] = tf2f(f2tf(k4.w));
            }
            {
                int pi = ((key >> 3) << 2) + (key & 3);
                int sv = (key >> 2) & 1;
                int vb = pi * 72 + j * 8 + sv;
                sVhi[vb + 0] = tf2f(f2tf(v4.x));
                sVhi[vb + 2] = tf2f(f2tf(v4.y));
                sVhi[vb + 4] = tf2f(f2tf(v4.z));
                sVhi[vb + 6] = tf2f(f2tf(v4.w));
            }
        }
        __syncthreads();

        // ---- S = Q K^T, sigmoid, store rna-rounded A to per-warp smem ----
#pragma unroll
        for (int nb = 0; nb < 8; nb++) {
            float s0[4] = {0.f, 0.f, 0.f, 0.f};
            float s1[4] = {0.f, 0.f, 0.f, 0.f};
#pragma unroll
            for (int ks = 0; ks < 4; ks++) {
                float2 bb = *reinterpret_cast<const float2*>(
                    &sK[((nb*8 + g) * 20 + ks*4 + tig) * 2]);
                unsigned b0 = __float_as_uint(bb.x);
                unsigned b1 = __float_as_uint(bb.y);
                mma_tf32(s0, qa[0][ks], b0, b1);
                mma_tf32(s1, qa[1][ks], b0, b1);
            }
            Aw[(g     ) * 72 + nb*8 + c0p    ] = tf2f(f2tf(sigm(s0[0])));
            Aw[(g     ) * 72 + nb*8 + c0p + 2] = tf2f(f2tf(sigm(s0[1])));
            Aw[(g +  8) * 72 + nb*8 + c0p    ] = tf2f(f2tf(sigm(s0[2])));
            Aw[(g +  8) * 72 + nb*8 + c0p + 2] = tf2f(f2tf(sigm(s0[3])));
            Aw[(g + 16) * 72 + nb*8 + c0p    ] = tf2f(f2tf(sigm(s1[0])));
            Aw[(g + 16) * 72 + nb*8 + c0p + 2] = tf2f(f2tf(sigm(s1[1])));
            Aw[(g + 24) * 72 + nb*8 + c0p    ] = tf2f(f2tf(sigm(s1[2])));
            Aw[(g + 24) * 72 + nb*8 + c0p + 2] = tf2f(f2tf(sigm(s1[3])));
        }
        __syncwarp();

        // ---- O += A V  (single tf32 term; all operands rna-rounded) ----
#pragma unroll
        for (int kk = 0; kk < 8; kk++) {
            unsigned a[2][4];
#pragma unroll
            for (int mt = 0; mt < 2; mt++) {
                float2 pA = *reinterpret_cast<const float2*>(
                    &Aw[(mt*16 + g    ) * 72 + kk*8 + 2*tig]);
                float2 pB = *reinterpret_cast<const float2*>(
                    &Aw[(mt*16 + g + 8) * 72 + kk*8 + 2*tig]);
                a[mt][0] = __float_as_uint(pA.x);
                a[mt][1] = __float_as_uint(pB.x);
                a[mt][2] = __float_as_uint(pA.y);
                a[mt][3] = __float_as_uint(pB.y);
            }
#pragma unroll
            for (int nb = 0; nb < 4; nb++) {
                float2 vh2 = *reinterpret_cast<const float2*>(
                    &sVhi[(kk*4 + tig) * 72 + (nb*8 + g) * 2]);
                unsigned b0h = __float_as_uint(vh2.x), b1h = __float_as_uint(vh2.y);
                mma_tf32(oc[0][nb], a[0], b0h, b1h);
                mma_tf32(oc[1][nb], a[1], b0h, b1h);
            }
        }
        __syncthreads();
    }

    // ---- store O ----
#pragma unroll
    for (int mt = 0; mt < 2; mt++)
#pragma unroll
        for (int nb = 0; nb < 4; nb++) {
            float2 v01; v01.x = oc[mt][nb][0]; v01.y = oc[mt][nb][1];
            float2 v23; v23.x = oc[mt][nb][2]; v23.y = oc[mt][nb][3];
            *reinterpret_cast<float2*>(&Og[(size_t)(mt*16 + g    ) * DD + nb*8 + 2*tig]) = v01;
            *reinterpret_cast<float2*>(&Og[(size_t)(mt*16 + g + 8) * DD + nb*8 + 2*tig]) = v23;
        }
}

// ---------------- tf32 mma GEMM, batched over grid.y (ROUND-8 PROVEN) -------
// out[z][M,128] = A @ W[z] + bias[z]  (3-term tf32 split)
// mode 0: plain ; mode 2: Ae = sum of NSPLIT partial-O slices; out = Ae + relu(Ae@W+b)
// GM=32, 128 threads (4 warps), each warp owns a 32-col group.
#define GM 32
#define AST 132   // smem row stride (floats): conflict-free
struct GemmJob {
    const float2* W[3];
    const float*  bias[3];
    float*        out[3];
};

__global__ __launch_bounds__(128, 6) void gemm_tf32_kernel(
    const float* __restrict__ A, GemmJob job, int mode)
{
    extern __shared__ float gsm[];
    float* Ah = gsm;               // [GM][AST]
    float* Al = gsm + GM * AST;    // [GM][AST]

    const int tid  = threadIdx.x;
    const int lane = tid & 31;
    const int cg   = tid >> 5;     // 4 warps = 4 column groups
    const int g    = lane >> 2;
    const int tig  = lane & 3;
    const int z    = blockIdx.y;
    const int blockRow = blockIdx.x * GM;

    const float2* __restrict__ Wsp  = job.W[z];
    const float*  __restrict__ bias = job.bias[z];
    float*        __restrict__ out  = job.out[z];

    // ---- stage A tile (32 x 128) pre-split into hi/lo ----
#pragma unroll
    for (int it = 0; it < 8; it++) {
        int f4 = it * 128 + tid;          // 1024 float4 total
        int r  = f4 >> 5;
        int c  = (f4 & 31) << 2;
        size_t off = (size_t)(blockRow + r) * DD + c;
        float4 v = *reinterpret_cast<const float4*>(&A[off]);
        if (mode == 2) {
#pragma unroll
            for (int s = 1; s < NSPLIT; s++) {
                float4 v2 = *reinterpret_cast<const float4*>(&A[off + (size_t)s * MTOT * DD]);
                v.x += v2.x; v.y += v2.y; v.z += v2.z; v.w += v2.w;
            }
        }
        float vs[4] = {v.x, v.y, v.z, v.w};
        float hi4[4], lo4[4];
#pragma unroll
        for (int i = 0; i < 4; i++) {
            hi4[i] = tf2f(f2tf(vs[i]));
            lo4[i] = tf2f(f2tf(vs[i] - hi4[i]));
        }
        *reinterpret_cast<float4*>(&Ah[r * AST + c]) = make_float4(hi4[0], hi4[1], hi4[2], hi4[3]);
        *reinterpret_cast<float4*>(&Al[r * AST + c]) = make_float4(lo4[0], lo4[1], lo4[2], lo4[3]);
    }
    __syncthreads();

    float oc[2][4][4];
#pragma unroll
    for (int mt = 0; mt < 2; mt++)
#pragma unroll
        for (int nb = 0; nb < 4; nb++)
#pragma unroll
            for (int i = 0; i < 4; i++) oc[mt][nb][i] = 0.f;

    const int ncol = cg * 32 + g;

    // W double buffer
    float2 wbuf0[4][2], wbuf1[4][2];
#define LOADW(kc, buf)                                                        \
    {                                                                         \
        _Pragma("unroll")                                                     \
        for (int nb = 0; nb < 4; nb++) {                                      \
            buf[nb][0] = Wsp[((kc) * 8 + tig    ) * DD + ncol + nb * 8];      \
            buf[nb][1] = Wsp[((kc) * 8 + tig + 4) * DD + ncol + nb * 8];      \
        }                                                                     \
    }

#define COMPUTE(kc, buf)                                                      \
    {                                                                         \
        unsigned ah[2][4], al[2][4];                                          \
        _Pragma("unroll")                                                     \
        for (int mt = 0; mt < 2; mt++) {                                      \
            int r0 = mt * 16 + g;                                             \
            ah[mt][0] = __float_as_uint(Ah[(r0    ) * AST + (kc)*8 + tig    ]);\
            ah[mt][1] = __float_as_uint(Ah[(r0 + 8) * AST + (kc)*8 + tig    ]);\
            ah[mt][2] = __float_as_uint(Ah[(r0    ) * AST + (kc)*8 + tig + 4]);\
            ah[mt][3] = __float_as_uint(Ah[(r0 + 8) * AST + (kc)*8 + tig + 4]);\
            al[mt][0] = __float_as_uint(Al[(r0    ) * AST + (kc)*8 + tig    ]);\
            al[mt][1] = __float_as_uint(Al[(r0 + 8) * AST + (kc)*8 + tig    ]);\
            al[mt][2] = __float_as_uint(Al[(r0    ) * AST + (kc)*8 + tig + 4]);\
            al[mt][3] = __float_as_uint(Al[(r0 + 8) * AST + (kc)*8 + tig + 4]);\
        }                                                                     \
        _Pragma("unroll")                                                     \
        for (int nb = 0; nb < 4; nb++) {                                      \
            unsigned b0h = __float_as_uint(buf[nb][0].x);                     \
            unsigned b1h = __float_as_uint(buf[nb][1].x);                     \
            unsigned b0l = __float_as_uint(buf[nb][0].y);                     \
            unsigned b1l = __float_as_uint(buf[nb][1].y);                     \
            _Pragma("unroll")                                                 \
            for (int mt = 0; mt < 2; mt++) {                                  \
                mma_tf32(oc[mt][nb], ah[mt], b0h, b1h);                       \
                mma_tf32(oc[mt][nb], al[mt], b0h, b1h);                       \
                mma_tf32(oc[mt][nb], ah[mt], b0l, b1l);                       \
            }                                                                 \
        }                                                                     \
    }

    LOADW(0, wbuf0);
#pragma unroll
    for (int kc2 = 0; kc2 < 8; kc2++) {
        LOADW(2 * kc2 + 1, wbuf1);
        COMPUTE(2 * kc2, wbuf0);
        if (kc2 < 7) LOADW(2 * kc2 + 2, wbuf0);
        COMPUTE(2 * kc2 + 1, wbuf1);
    }

    // epilogue (mode-2 residual = hi + lo from smem)
#pragma unroll
    for (int mt = 0; mt < 2; mt++) {
        int rloc0 = mt * 16 + g;
        int row0  = blockRow + rloc0;
#pragma unroll
        for (int nb = 0; nb < 4; nb++) {
            int col = cg * 32 + nb * 8 + 2 * tig;
            float2 bi = *reinterpret_cast<const float2*>(&bias[col]);
            float v0 = oc[mt][nb][0] + bi.x;
            float v1 = oc[mt][nb][1] + bi.y;
            float v2 = oc[mt][nb][2] + bi.x;
            float v3 = oc[mt][nb][3] + bi.y;
            if (mode == 2) {
                v0 = (Ah[rloc0*AST + col]     + Al[rloc0*AST + col])     + fmaxf(v0, 0.f);
                v1 = (Ah[rloc0*AST + col + 1] + Al[rloc0*AST + col + 1]) + fmaxf(v1, 0.f);
                v2 = (Ah[(rloc0+8)*AST + col]   + Al[(rloc0+8)*AST + col])   + fmaxf(v2, 0.f);
                v3 = (Ah[(rloc0+8)*AST + col+1] + Al[(rloc0+8)*AST + col+1]) + fmaxf(v3, 0.f);
            }
            float2 s01; s01.x = v0; s01.y = v1;
            float2 s23; s23.x = v2; s23.y = v3;
            *reinterpret_cast<float2*>(&out[(size_t)row0 * DD + col]) = s01;
            *reinterpret_cast<float2*>(&out[(size_t)(row0 + 8) * DD + col]) = s23;
        }
    }
#undef LOADW
#undef COMPUTE
}

// ---------------- PMA attention (with in-block seed projection) -------------
__global__ __launch_bounds__(1024) void pma_attn_kernel(
    const float* __restrict__ S, const float* __restrict__ Wq,
    const float* __restrict__ bq,
    const float* __restrict__ K, const float* __restrict__ V,
    float* __restrict__ P)
{
    const int h = blockIdx.x;
    const int b = blockIdx.y;

    __shared__ float sqv[DD];
    if (threadIdx.x < DD) {
        int n = threadIdx.x;
        float s = 0.f;
#pragma unroll 4
        for (int k = 0; k < DD; k++) s += S[k] * Wq[(size_t)k * DD + n];
        sqv[n] = s + bq[n];
    }
    __syncthreads();

    float q[DH], o[DH];
#pragma unroll
    for (int d = 0; d < DH; d++) { q[d] = sqv[h * DH + d]; o[d] = 0.f; }

    const float* Kb = K + ((size_t)b * NN) * DD + h * DH;
    const float* Vb = V + ((size_t)b * NN) * DD + h * DH;

    for (int m = threadIdx.x; m < NN; m += blockDim.x) {
        const float* kr = Kb + (size_t)m * DD;
        float s0 = 0.f, s1 = 0.f, s2 = 0.f, s3 = 0.f;
#pragma unroll
        for (int d = 0; d < DH; d += 4) {
            float4 kv = *reinterpret_cast<const float4*>(kr + d);
            s0 += q[d] * kv.x; s1 += q[d + 1] * kv.y;
            s2 += q[d + 2] * kv.z; s3 += q[d + 3] * kv.w;
        }
        float a = sigm((s0 + s1) + (s2 + s3));
        const float* vr = Vb + (size_t)m * DD;
#pragma unroll
        for (int d = 0; d < DH; d += 4) {
            float4 vv = *reinterpret_cast<const float4*>(vr + d);
            o[d]     += a * vv.x; o[d + 1] += a * vv.y;
            o[d + 2] += a * vv.z; o[d + 3] += a * vv.w;
        }
    }

    __shared__ float red[32][DH];
    int lane = threadIdx.x & 31, wid = threadIdx.x >> 5;
#pragma unroll
    for (int d = 0; d < DH; d++) {
        float v = o[d];
        for (int off = 16; off > 0; off >>= 1) v += __shfl_down_sync(0xffffffffu, v, off);
        o[d] = v;
    }
    if (lane == 0) {
#pragma unroll
        for (int d = 0; d < DH; d++) red[wid][d] = o[d];
    }
    __syncthreads();
    if (threadIdx.x < DH) {
        float s = q[threadIdx.x];   // residual Qh
#pragma unroll
        for (int w = 0; w < 32; w++) s += red[w][threadIdx.x];
        P[(size_t)b * DD + h * DH + threadIdx.x] = s;
    }
}

// ---------------- PMA FFN + final projection --------------------------------
__global__ __launch_bounds__(256) void pma_final_kernel(
    const float* __restrict__ P, const float* __restrict__ Wo,
    const float* __restrict__ bo, const float* __restrict__ pW,
    const float* __restrict__ pb, float* __restrict__ out)
{
    const int b = blockIdx.x;
    __shared__ float O[DD];
    __shared__ float P0[DD];
    int t = threadIdx.x;
    if (t < DD) O[t] = P[(size_t)b * DD + t];
    __syncthreads();
    if (t < DD) {
        float s = 0.f;
#pragma unroll 4
        for (int k = 0; k < DD; k++) s += O[k] * Wo[(size_t)k * DD + t];
        P0[t] = O[t] + fmaxf(s + bo[t], 0.f);
    }
    __syncthreads();
    {
        float s = 0.f;
#pragma unroll 4
        for (int k = 0; k < DD; k++) s += P0[k] * pW[(size_t)k * DOUT + t];
        out[(size_t)b * DOUT + t] = s + pb[t];
    }
}

// ---------------- host launcher -------------------------------------------
extern "C" void kernel_launch(void* const* d_in, const int* in_sizes, int n_in,
                              void* d_out, int out_size)
{
    const float* X = (const float*)d_in[0];
    const float* m0[8]; const float* m1[8]; const float* m2[8];
    for (int j = 0; j < 8; j++) { m0[j] = (const float*)d_in[1 + j];
                                  m1[j] = (const float*)d_in[9 + j];
                                  m2[j] = (const float*)d_in[17 + j]; }
    const float* S  = (const float*)d_in[25];
    const float* pW = (const float*)d_in[26];
    const float* pb = (const float*)d_in[27];
    float* out = (float*)d_out;

    float *Qb, *Kb, *Vb, *Ob, *Xb, *Pb;
    float2* Wsp;
    cudaGetSymbolAddress((void**)&Qb, g_Q);
    cudaGetSymbolAddress((void**)&Kb, g_K);
    cudaGetSymbolAddress((void**)&Vb, g_V);
    cudaGetSymbolAddress((void**)&Ob, g_O);
    cudaGetSymbolAddress((void**)&Xb, g_X);
    cudaGetSymbolAddress((void**)&Pb, g_P);
    cudaGetSymbolAddress((void**)&Wsp, g_Wsp);

    const int attn_smem = SMEM_F * 4;            // 55 KB
    const int gemm_smem = 2 * GM * AST * 4;      // 33.8 KB
    cudaFuncSetAttribute(attn_mma_kernel,
                         cudaFuncAttributeMaxDynamicSharedMemorySize, attn_smem);
    cudaFuncSetAttribute(gemm_tf32_kernel,
                         cudaFuncAttributeMaxDynamicSharedMemorySize, gemm_smem);

    // ---- pre-split all weights in one launch ----
    WPtrs wp;
    const float* wmats[NW] = { m0[0], m0[2], m0[4], m0[6],
                               m1[0], m1[2], m1[4], m1[6],
                               m2[2], m2[4] };
    for (int i = 0; i < NW; i++) wp.w[i] = wmats[i];
    wsplit_all_kernel<<<(NW*DD*DD)/256, 256>>>(wp, Wsp);
    #define WSLOT(i) (Wsp + (size_t)(i)*DD*DD)

    dim3 agrid(NN / 128, HH * NSPLIT, BB);       // (16, 8, 4) = 512 CTAs

    GemmJob j;

    // ---- SAB 0: QKV batched ----
    j.W[0] = WSLOT(0); j.bias[0] = m0[1]; j.out[0] = Qb;
    j.W[1] = WSLOT(1); j.bias[1] = m0[3]; j.out[1] = Kb;
    j.W[2] = WSLOT(2); j.bias[2] = m0[5]; j.out[2] = Vb;
    gemm_tf32_kernel<<<dim3(MTOT/GM, 3), 128, gemm_smem>>>(X, j, 0);
    attn_mma_kernel<<<agrid, 128, attn_smem>>>(Qb, Kb, Vb, Ob);
    j.W[0] = WSLOT(3); j.bias[0] = m0[7]; j.out[0] = Xb;
    gemm_tf32_kernel<<<dim3(MTOT/GM, 1), 128, gemm_smem>>>(Ob, j, 2);

    // ---- SAB 1: QKV batched ----
    j.W[0] = WSLOT(4); j.bias[0] = m1[1]; j.out[0] = Qb;
    j.W[1] = WSLOT(5); j.bias[1] = m1[3]; j.out[1] = Kb;
    j.W[2] = WSLOT(6); j.bias[2] = m1[5]; j.out[2] = Vb;
    gemm_tf32_kernel<<<dim3(MTOT/GM, 3), 128, gemm_smem>>>(Xb, j, 0);
    attn_mma_kernel<<<agrid, 128, attn_smem>>>(Qb, Kb, Vb, Ob);
    j.W[0] = WSLOT(7); j.bias[0] = m1[7]; j.out[0] = Qb;   // SAB1 out -> Qb
    gemm_tf32_kernel<<<dim3(MTOT/GM, 1), 128, gemm_smem>>>(Ob, j, 2);

    // ---- PMA: K,V batched; qvec folded into pma_attn ----
    j.W[0] = WSLOT(8); j.bias[0] = m2[3]; j.out[0] = Kb;
    j.W[1] = WSLOT(9); j.bias[1] = m2[5]; j.out[1] = Vb;
    gemm_tf32_kernel<<<dim3(MTOT/GM, 2), 128, gemm_smem>>>(Qb, j, 0);
    pma_attn_kernel<<<dim3(HH, BB), 1024>>>(S, m2[0], m2[1], Kb, Vb, Pb);
    pma_final_kernel<<<BB, 256>>>(Pb, m2[6], m2[7], pW, pb, out);

    (void)in_sizes; (void)n_in; (void)out_size;
}

// round 17
// speedup vs baseline: 1.0449x; 1.0449x over previous
#include <cuda_runtime.h>
#include <math.h>

typedef unsigned long long ull;

// Problem constants
#define BB 4
#define NN 2048
#define DD 128
#define HH 4
#define DH 32
#define DOUT 256
#define MTOT (BB*NN)          // 8192
#define SCALE 0.088388347648318440550f  // 1/sqrt(128)
#define HALF_SCALE 0.044194173824159220275f // SCALE/2
#define NSPLIT 4
#define KEYS_PER_SPLIT (NN/NSPLIT)
#define NW 10                  // number of pre-split weight matrices

// ---------------- scratch (device globals; no allocations allowed) ----------
__device__ float g_Q[MTOT*DD];
__device__ float g_K[MTOT*DD];
__device__ float g_V[MTOT*DD];
__device__ float g_O[NSPLIT*MTOT*DD];   // split partial attention outputs
__device__ float g_X[MTOT*DD];
__device__ float g_P[BB*DD];
__device__ float2 g_Wsp[NW*DD*DD];      // pre-split weights (hi, lo)

// ---------------- tf32 helpers ----------------------------------------------
__device__ __forceinline__ unsigned f2tf(float f) {
    unsigned u; asm("cvt.rna.tf32.f32 %0, %1;" : "=r"(u) : "f"(f)); return u;
}
__device__ __forceinline__ float tf2f(unsigned u) { return __uint_as_float(u); }

__device__ __forceinline__ void mma_tf32(float c[4], const unsigned a[4],
                                         unsigned b0, unsigned b1) {
    asm volatile(
        "mma.sync.aligned.m16n8k8.row.col.f32.tf32.tf32.f32 "
        "{%0,%1,%2,%3}, {%4,%5,%6,%7}, {%8,%9}, {%0,%1,%2,%3};"
        : "+f"(c[0]), "+f"(c[1]), "+f"(c[2]), "+f"(c[3])
        : "r"(a[0]), "r"(a[1]), "r"(a[2]), "r"(a[3]), "r"(b0), "r"(b1));
}

// sigmoid via MUFU.TANH: sigm(dot*SCALE) = 0.5*tanh(dot*SCALE/2) + 0.5
__device__ __forceinline__ float sigm(float dot) {
    float t;
    asm("tanh.approx.f32 %0, %1;" : "=f"(t) : "f"(dot * HALF_SCALE));
    return fmaf(0.5f, t, 0.5f);
}

// ---------------- fused weight pre-split (vectorized, one launch) ------------
struct WPtrs { const float* w[NW]; };

__global__ void wsplit_all_kernel(WPtrs p, float2* __restrict__ out)
{
    int i4 = blockIdx.x * 256 + threadIdx.x;    // grid = NW*DD*DD/4 float4's
    int slot = i4 >> 12;                         // DD*DD/4 = 4096 = 2^12
    int off4 = i4 & 4095;
    float4 v = *reinterpret_cast<const float4*>(p.w[slot] + off4 * 4);
    float vs[4] = {v.x, v.y, v.z, v.w};
    float2* o = out + ((size_t)slot << 14) + off4 * 4;
#pragma unroll
    for (int k = 0; k < 4; k++) {
        float hi = tf2f(f2tf(vs[k]));
        o[k] = make_float2(hi, tf2f(f2tf(vs[k] - hi)));
    }
}

// ---------------- tf32 mma flash sigmoid-attention (ROUND-8 PROVEN) ---------
// Per CTA: (b, h, split, qtile of 128 rows). 4 warps, each warp: 32 q-rows.
// Key tiles of 64. O_part[split] = (split==0 ? Qh : 0) + sigmoid(QK^T*s)V.
// This exact configuration (NSPLIT=4, occupancy 4, m32n32 warp tiles,
// A round-trip through per-warp smem) survived 8 controlled perturbations
// (retilings, fission, prefetch, fusion, split-factor changes) — all were
// neutral or regressions. Treat as frozen.
// IMPORTANT: all tf32 operands are rounded with cvt.rna (round-to-nearest).
// Relying on the tensor core's implicit truncation introduces a SYSTEMATIC
// bias on the (strictly positive) attention weights that accumulates over
// the 2048-key reduction — measured 22x rel_err blowup. Do not remove.
#define SK_F   (64*40)        // 2560 floats
#define SV_F   (32*72)        // 2304 floats
#define SA_F   (32*72)        // per warp
#define SMEM_F (SK_F + SV_F + 4*SA_F)   // 14080 floats = 55 KB

__global__ __launch_bounds__(128, 4) void attn_mma_kernel(
    const float* __restrict__ Q, const float* __restrict__ K,
    const float* __restrict__ V, float* __restrict__ O)
{
    extern __shared__ float smem[];
    float* sK   = smem;
    float* sVhi = smem + SK_F;
    float* sA   = sVhi + SV_F;

    const int w    = threadIdx.x >> 5;
    const int lane = threadIdx.x & 31;
    const int g    = lane >> 2;
    const int tig  = lane & 3;

    const int qt    = blockIdx.x;
    const int h     = blockIdx.y & 3;
    const int split = blockIdx.y >> 2;
    const int b     = blockIdx.z;

    float* Aw = sA + w * SA_F;

    const float* Qw = Q + ((size_t)b * NN + qt * 128 + w * 32) * DD + h * DH;
    const float* Kg = K + (size_t)b * NN * DD + h * DH + (size_t)split * KEYS_PER_SPLIT * DD;
    const float* Vg = V + (size_t)b * NN * DD + h * DH + (size_t)split * KEYS_PER_SPLIT * DD;
    float* Og = O + (size_t)split * MTOT * DD + ((size_t)b * NN + qt * 128 + w * 32) * DD + h * DH;

    // Q fragments (tf32, rounded once)
    unsigned qa[2][4][4];
#pragma unroll
    for (int mt = 0; mt < 2; mt++)
#pragma unroll
        for (int ks = 0; ks < 4; ks++) {
            qa[mt][ks][0] = f2tf(Qw[(mt*16 + g    ) * DD + ks*8 + tig    ]);
            qa[mt][ks][1] = f2tf(Qw[(mt*16 + g + 8) * DD + ks*8 + tig    ]);
            qa[mt][ks][2] = f2tf(Qw[(mt*16 + g    ) * DD + ks*8 + tig + 4]);
            qa[mt][ks][3] = f2tf(Qw[(mt*16 + g + 8) * DD + ks*8 + tig + 4]);
        }

    // O accumulators; residual Qh in split 0
    float oc[2][4][4];
#pragma unroll
    for (int mt = 0; mt < 2; mt++)
#pragma unroll
        for (int nb = 0; nb < 4; nb++) {
            if (split == 0) {
                oc[mt][nb][0] = Qw[(mt*16 + g    ) * DD + nb*8 + 2*tig    ];
                oc[mt][nb][1] = Qw[(mt*16 + g    ) * DD + nb*8 + 2*tig + 1];
                oc[mt][nb][2] = Qw[(mt*16 + g + 8) * DD + nb*8 + 2*tig    ];
                oc[mt][nb][3] = Qw[(mt*16 + g + 8) * DD + nb*8 + 2*tig + 1];
            } else {
                oc[mt][nb][0] = oc[mt][nb][1] = oc[mt][nb][2] = oc[mt][nb][3] = 0.f;
            }
        }

    const int c0p = (tig >> 1) + ((tig & 1) << 2);  // permuted col: {0,4,1,5}

    for (int kt = 0; kt < KEYS_PER_SPLIT / 64; kt++) {
        // ---- load K/V tile (64 keys x 32 dims), tf32-rounded (rna) ----
#pragma unroll
        for (int r = 0; r < 4; r++) {
            int gi  = r * 128 + threadIdx.x;
            int key = gi >> 3;
            int j   = gi & 7;
            const float4 k4 = *reinterpret_cast<const float4*>(
                Kg + (size_t)(kt * 64 + key) * DD + j * 4);
            const float4 v4 = *reinterpret_cast<const float4*>(
                Vg + (size_t)(kt * 64 + key) * DD + j * 4);
            {
                int base = key * 40 + (j >> 1) * 8 + (j & 1);
                sK[base + 0] = tf2f(f2tf(k4.x));
                sK[base + 2] = tf2f(f2tf(k4.y));
                sK[base + 4] = tf2f(f2tf(k4.z));
                sK[base + 6] = tf2f(f2tf(k4.w));
            }
            {
                int pi = ((key >> 3) << 2) + (key & 3);
                int sv = (key >> 2) & 1;
                int vb = pi * 72 + j * 8 + sv;
                sVhi[vb + 0] = tf2f(f2tf(v4.x));
                sVhi[vb + 2] = tf2f(f2tf(v4.y));
                sVhi[vb + 4] = tf2f(f2tf(v4.z));
                sVhi[vb + 6] = tf2f(f2tf(v4.w));
            }
        }
        __syncthreads();

        // ---- S = Q K^T, sigmoid, store rna-rounded A to per-warp smem ----
#pragma unroll
        for (int nb = 0; nb < 8; nb++) {
            float s0[4] = {0.f, 0.f, 0.f, 0.f};
            float s1[4] = {0.f, 0.f, 0.f, 0.f};
#pragma unroll
            for (int ks = 0; ks < 4; ks++) {
                float2 bb = *reinterpret_cast<const float2*>(
                    &sK[((nb*8 + g) * 20 + ks*4 + tig) * 2]);
                unsigned b0 = __float_as_uint(bb.x);
                unsigned b1 = __float_as_uint(bb.y);
                mma_tf32(s0, qa[0][ks], b0, b1);
                mma_tf32(s1, qa[1][ks], b0, b1);
            }
            Aw[(g     ) * 72 + nb*8 + c0p    ] = tf2f(f2tf(sigm(s0[0])));
            Aw[(g     ) * 72 + nb*8 + c0p + 2] = tf2f(f2tf(sigm(s0[1])));
            Aw[(g +  8) * 72 + nb*8 + c0p    ] = tf2f(f2tf(sigm(s0[2])));
            Aw[(g +  8) * 72 + nb*8 + c0p + 2] = tf2f(f2tf(sigm(s0[3])));
            Aw[(g + 16) * 72 + nb*8 + c0p    ] = tf2f(f2tf(sigm(s1[0])));
            Aw[(g + 16) * 72 + nb*8 + c0p + 2] = tf2f(f2tf(sigm(s1[1])));
            Aw[(g + 24) * 72 + nb*8 + c0p    ] = tf2f(f2tf(sigm(s1[2])));
            Aw[(g + 24) * 72 + nb*8 + c0p + 2] = tf2f(f2tf(sigm(s1[3])));
        }
        __syncwarp();

        // ---- O += A V  (single tf32 term; all operands rna-rounded) ----
#pragma unroll
        for (int kk = 0; kk < 8; kk++) {
            unsigned a[2][4];
#pragma unroll
            for (int mt = 0; mt < 2; mt++) {
                float2 pA = *reinterpret_cast<const float2*>(
                    &Aw[(mt*16 + g    ) * 72 + kk*8 + 2*tig]);
                float2 pB = *reinterpret_cast<const float2*>(
                    &Aw[(mt*16 + g + 8) * 72 + kk*8 + 2*tig]);
                a[mt][0] = __float_as_uint(pA.x);
                a[mt][1] = __float_as_uint(pB.x);
                a[mt][2] = __float_as_uint(pA.y);
                a[mt][3] = __float_as_uint(pB.y);
            }
#pragma unroll
            for (int nb = 0; nb < 4; nb++) {
                float2 vh2 = *reinterpret_cast<const float2*>(
                    &sVhi[(kk*4 + tig) * 72 + (nb*8 + g) * 2]);
                unsigned b0h = __float_as_uint(vh2.x), b1h = __float_as_uint(vh2.y);
                mma_tf32(oc[0][nb], a[0], b0h, b1h);
                mma_tf32(oc[1][nb], a[1], b0h, b1h);
            }
        }
        __syncthreads();
    }

    // ---- store O ----
#pragma unroll
    for (int mt = 0; mt < 2; mt++)
#pragma unroll
        for (int nb = 0; nb < 4; nb++) {
            float2 v01; v01.x = oc[mt][nb][0]; v01.y = oc[mt][nb][1];
            float2 v23; v23.x = oc[mt][nb][2]; v23.y = oc[mt][nb][3];
            *reinterpret_cast<float2*>(&Og[(size_t)(mt*16 + g    ) * DD + nb*8 + 2*tig]) = v01;
            *reinterpret_cast<float2*>(&Og[(size_t)(mt*16 + g + 8) * DD + nb*8 + 2*tig]) = v23;
        }
}

// ---------------- tf32 mma GEMM, batched over grid.y (ROUND-8 PROVEN) -------
// out[z][M,128] = A @ W[z] + bias[z]  (3-term tf32 split)
// mode 0: plain ; mode 2: Ae = sum of NSPLIT partial-O slices; out = Ae + relu(Ae@W+b)
// GM=32, 128 threads (4 warps), each warp owns a 32-col group.
#define GM 32
#define AST 132   // smem row stride (floats): conflict-free
struct GemmJob {
    const float2* W[3];
    const float*  bias[3];
    float*        out[3];
};

__global__ __launch_bounds__(128, 6) void gemm_tf32_kernel(
    const float* __restrict__ A, GemmJob job, int mode)
{
    extern __shared__ float gsm[];
    float* Ah = gsm;               // [GM][AST]
    float* Al = gsm + GM * AST;    // [GM][AST]

    const int tid  = threadIdx.x;
    const int lane = tid & 31;
    const int cg   = tid >> 5;     // 4 warps = 4 column groups
    const int g    = lane >> 2;
    const int tig  = lane & 3;
    const int z    = blockIdx.y;
    const int blockRow = blockIdx.x * GM;

    const float2* __restrict__ Wsp  = job.W[z];
    const float*  __restrict__ bias = job.bias[z];
    float*        __restrict__ out  = job.out[z];

    // ---- stage A tile (32 x 128) pre-split into hi/lo ----
#pragma unroll
    for (int it = 0; it < 8; it++) {
        int f4 = it * 128 + tid;          // 1024 float4 total
        int r  = f4 >> 5;
        int c  = (f4 & 31) << 2;
        size_t off = (size_t)(blockRow + r) * DD + c;
        float4 v = *reinterpret_cast<const float4*>(&A[off]);
        if (mode == 2) {
#pragma unroll
            for (int s = 1; s < NSPLIT; s++) {
                float4 v2 = *reinterpret_cast<const float4*>(&A[off + (size_t)s * MTOT * DD]);
                v.x += v2.x; v.y += v2.y; v.z += v2.z; v.w += v2.w;
            }
        }
        float vs[4] = {v.x, v.y, v.z, v.w};
        float hi4[4], lo4[4];
#pragma unroll
        for (int i = 0; i < 4; i++) {
            hi4[i] = tf2f(f2tf(vs[i]));
            lo4[i] = tf2f(f2tf(vs[i] - hi4[i]));
        }
        *reinterpret_cast<float4*>(&Ah[r * AST + c]) = make_float4(hi4[0], hi4[1], hi4[2], hi4[3]);
        *reinterpret_cast<float4*>(&Al[r * AST + c]) = make_float4(lo4[0], lo4[1], lo4[2], lo4[3]);
    }
    __syncthreads();

    float oc[2][4][4];
#pragma unroll
    for (int mt = 0; mt < 2; mt++)
#pragma unroll
        for (int nb = 0; nb < 4; nb++)
#pragma unroll
            for (int i = 0; i < 4; i++) oc[mt][nb][i] = 0.f;

    const int ncol = cg * 32 + g;

    // W double buffer
    float2 wbuf0[4][2], wbuf1[4][2];
#define LOADW(kc, buf)                                                        \
    {                                                                         \
        _Pragma("unroll")                                                     \
        for (int nb = 0; nb < 4; nb++) {                                      \
            buf[nb][0] = Wsp[((kc) * 8 + tig    ) * DD + ncol + nb * 8];      \
            buf[nb][1] = Wsp[((kc) * 8 + tig + 4) * DD + ncol + nb * 8];      \
        }                                                                     \
    }

#define COMPUTE(kc, buf)                                                      \
    {                                                                         \
        unsigned ah[2][4], al[2][4];                                          \
        _Pragma("unroll")                                                     \
        for (int mt = 0; mt < 2; mt++) {                                      \
            int r0 = mt * 16 + g;                                             \
            ah[mt][0] = __float_as_uint(Ah[(r0    ) * AST + (kc)*8 + tig    ]);\
            ah[mt][1] = __float_as_uint(Ah[(r0 + 8) * AST + (kc)*8 + tig    ]);\
            ah[mt][2] = __float_as_uint(Ah[(r0    ) * AST + (kc)*8 + tig + 4]);\
            ah[mt][3] = __float_as_uint(Ah[(r0 + 8) * AST + (kc)*8 + tig + 4]);\
            al[mt][0] = __float_as_uint(Al[(r0    ) * AST + (kc)*8 + tig    ]);\
            al[mt][1] = __float_as_uint(Al[(r0 + 8) * AST + (kc)*8 + tig    ]);\
            al[mt][2] = __float_as_uint(Al[(r0    ) * AST + (kc)*8 + tig + 4]);\
            al[mt][3] = __float_as_uint(Al[(r0 + 8) * AST + (kc)*8 + tig + 4]);\
        }                                                                     \
        _Pragma("unroll")                                                     \
        for (int nb = 0; nb < 4; nb++) {                                      \
            unsigned b0h = __float_as_uint(buf[nb][0].x);                     \
            unsigned b1h = __float_as_uint(buf[nb][1].x);                     \
            unsigned b0l = __float_as_uint(buf[nb][0].y);                     \
            unsigned b1l = __float_as_uint(buf[nb][1].y);                     \
            _Pragma("unroll")                                                 \
            for (int mt = 0; mt < 2; mt++) {                                  \
                mma_tf32(oc[mt][nb], ah[mt], b0h, b1h);                       \
                mma_tf32(oc[mt][nb], al[mt], b0h, b1h);                       \
                mma_tf32(oc[mt][nb], ah[mt], b0l, b1l);                       \
            }                                                                 \
        }                                                                     \
    }

    LOADW(0, wbuf0);
#pragma unroll
    for (int kc2 = 0; kc2 < 8; kc2++) {
        LOADW(2 * kc2 + 1, wbuf1);
        COMPUTE(2 * kc2, wbuf0);
        if (kc2 < 7) LOADW(2 * kc2 + 2, wbuf0);
        COMPUTE(2 * kc2 + 1, wbuf1);
    }

    // epilogue (mode-2 residual = hi + lo from smem)
#pragma unroll
    for (int mt = 0; mt < 2; mt++) {
        int rloc0 = mt * 16 + g;
        int row0  = blockRow + rloc0;
#pragma unroll
        for (int nb = 0; nb < 4; nb++) {
            int col = cg * 32 + nb * 8 + 2 * tig;
            float2 bi = *reinterpret_cast<const float2*>(&bias[col]);
            float v0 = oc[mt][nb][0] + bi.x;
            float v1 = oc[mt][nb][1] + bi.y;
            float v2 = oc[mt][nb][2] + bi.x;
            float v3 = oc[mt][nb][3] + bi.y;
            if (mode == 2) {
                v0 = (Ah[rloc0*AST + col]     + Al[rloc0*AST + col])     + fmaxf(v0, 0.f);
                v1 = (Ah[rloc0*AST + col + 1] + Al[rloc0*AST + col + 1]) + fmaxf(v1, 0.f);
                v2 = (Ah[(rloc0+8)*AST + col]   + Al[(rloc0+8)*AST + col])   + fmaxf(v2, 0.f);
                v3 = (Ah[(rloc0+8)*AST + col+1] + Al[(rloc0+8)*AST + col+1]) + fmaxf(v3, 0.f);
            }
            float2 s01; s01.x = v0; s01.y = v1;
            float2 s23; s23.x = v2; s23.y = v3;
            *reinterpret_cast<float2*>(&out[(size_t)row0 * DD + col]) = s01;
            *reinterpret_cast<float2*>(&out[(size_t)(row0 + 8) * DD + col]) = s23;
        }
    }
#undef LOADW
#undef COMPUTE
}

// ---------------- PMA attention (with in-block seed projection) -------------
__global__ __launch_bounds__(1024) void pma_attn_kernel(
    const float* __restrict__ S, const float* __restrict__ Wq,
    const float* __restrict__ bq,
    const float* __restrict__ K, const float* __restrict__ V,
    float* __restrict__ P)
{
    const int h = blockIdx.x;
    const int b = blockIdx.y;

    __shared__ float sqv[DD];
    if (threadIdx.x < DD) {
        int n = threadIdx.x;
        float s = 0.f;
#pragma unroll 4
        for (int k = 0; k < DD; k++) s += S[k] * Wq[(size_t)k * DD + n];
        sqv[n] = s + bq[n];
    }
    __syncthreads();

    float q[DH], o[DH];
#pragma unroll
    for (int d = 0; d < DH; d++) { q[d] = sqv[h * DH + d]; o[d] = 0.f; }

    const float* Kb = K + ((size_t)b * NN) * DD + h * DH;
    const float* Vb = V + ((size_t)b * NN) * DD + h * DH;

    for (int m = threadIdx.x; m < NN; m += blockDim.x) {
        const float* kr = Kb + (size_t)m * DD;
        float s0 = 0.f, s1 = 0.f, s2 = 0.f, s3 = 0.f;
#pragma unroll
        for (int d = 0; d < DH; d += 4) {
            float4 kv = *reinterpret_cast<const float4*>(kr + d);
            s0 += q[d] * kv.x; s1 += q[d + 1] * kv.y;
            s2 += q[d + 2] * kv.z; s3 += q[d + 3] * kv.w;
        }
        float a = sigm((s0 + s1) + (s2 + s3));
        const float* vr = Vb + (size_t)m * DD;
#pragma unroll
        for (int d = 0; d < DH; d += 4) {
            float4 vv = *reinterpret_cast<const float4*>(vr + d);
            o[d]     += a * vv.x; o[d + 1] += a * vv.y;
            o[d + 2] += a * vv.z; o[d + 3] += a * vv.w;
        }
    }

    __shared__ float red[32][DH];
    int lane = threadIdx.x & 31, wid = threadIdx.x >> 5;
#pragma unroll
    for (int d = 0; d < DH; d++) {
        float v = o[d];
        for (int off = 16; off > 0; off >>= 1) v += __shfl_down_sync(0xffffffffu, v, off);
        o[d] = v;
    }
    if (lane == 0) {
#pragma unroll
        for (int d = 0; d < DH; d++) red[wid][d] = o[d];
    }
    __syncthreads();
    if (threadIdx.x < DH) {
        float s = q[threadIdx.x];   // residual Qh
#pragma unroll
        for (int w = 0; w < 32; w++) s += red[w][threadIdx.x];
        P[(size_t)b * DD + h * DH + threadIdx.x] = s;
    }
}

// ---------------- PMA FFN + final projection --------------------------------
__global__ __launch_bounds__(256) void pma_final_kernel(
    const float* __restrict__ P, const float* __restrict__ Wo,
    const float* __restrict__ bo, const float* __restrict__ pW,
    const float* __restrict__ pb, float* __restrict__ out)
{
    const int b = blockIdx.x;
    __shared__ float O[DD];
    __shared__ float P0[DD];
    int t = threadIdx.x;
    if (t < DD) O[t] = P[(size_t)b * DD + t];
    __syncthreads();
    if (t < DD) {
        float s = 0.f;
#pragma unroll 4
        for (int k = 0; k < DD; k++) s += O[k] * Wo[(size_t)k * DD + t];
        P0[t] = O[t] + fmaxf(s + bo[t], 0.f);
    }
    __syncthreads();
    {
        float s = 0.f;
#pragma unroll 4
        for (int k = 0; k < DD; k++) s += P0[k] * pW[(size_t)k * DOUT + t];
        out[(size_t)b * DOUT + t] = s + pb[t];
    }
}

// ---------------- host launcher -------------------------------------------
extern "C" void kernel_launch(void* const* d_in, const int* in_sizes, int n_in,
                              void* d_out, int out_size)
{
    const float* X = (const float*)d_in[0];
    const float* m0[8]; const float* m1[8]; const float* m2[8];
    for (int j = 0; j < 8; j++) { m0[j] = (const float*)d_in[1 + j];
                                  m1[j] = (const float*)d_in[9 + j];
                                  m2[j] = (const float*)d_in[17 + j]; }
    const float* S  = (const float*)d_in[25];
    const float* pW = (const float*)d_in[26];
    const float* pb = (const float*)d_in[27];
    float* out = (float*)d_out;

    float *Qb, *Kb, *Vb, *Ob, *Xb, *Pb;
    float2* Wsp;
    cudaGetSymbolAddress((void**)&Qb, g_Q);
    cudaGetSymbolAddress((void**)&Kb, g_K);
    cudaGetSymbolAddress((void**)&Vb, g_V);
    cudaGetSymbolAddress((void**)&Ob, g_O);
    cudaGetSymbolAddress((void**)&Xb, g_X);
    cudaGetSymbolAddress((void**)&Pb, g_P);
    cudaGetSymbolAddress((void**)&Wsp, g_Wsp);

    const int attn_smem = SMEM_F * 4;            // 55 KB
    const int gemm_smem = 2 * GM * AST * 4;      // 33.8 KB
    cudaFuncSetAttribute(attn_mma_kernel,
                         cudaFuncAttributeMaxDynamicSharedMemorySize, attn_smem);
    cudaFuncSetAttribute(gemm_tf32_kernel,
                         cudaFuncAttributeMaxDynamicSharedMemorySize, gemm_smem);

    // ---- pre-split all weights in one vectorized launch ----
    WPtrs wp;
    const float* wmats[NW] = { m0[0], m0[2], m0[4], m0[6],
                               m1[0], m1[2], m1[4], m1[6],
                               m2[2], m2[4] };
    for (int i = 0; i < NW; i++) wp.w[i] = wmats[i];
    wsplit_all_kernel<<<(NW*DD*DD/4)/256, 256>>>(wp, Wsp);
    #define WSLOT(i) (Wsp + (size_t)(i)*DD*DD)

    dim3 agrid(NN / 128, HH * NSPLIT, BB);       // (16, 16, 4)

    GemmJob j;

    // ---- SAB 0: QKV batched ----
    j.W[0] = WSLOT(0); j.bias[0] = m0[1]; j.out[0] = Qb;
    j.W[1] = WSLOT(1); j.bias[1] = m0[3]; j.out[1] = Kb;
    j.W[2] = WSLOT(2); j.bias[2] = m0[5]; j.out[2] = Vb;
    gemm_tf32_kernel<<<dim3(MTOT/GM, 3), 128, gemm_smem>>>(X, j, 0);
    attn_mma_kernel<<<agrid, 128, attn_smem>>>(Qb, Kb, Vb, Ob);
    j.W[0] = WSLOT(3); j.bias[0] = m0[7]; j.out[0] = Xb;
    gemm_tf32_kernel<<<dim3(MTOT/GM, 1), 128, gemm_smem>>>(Ob, j, 2);

    // ---- SAB 1: QKV batched ----
    j.W[0] = WSLOT(4); j.bias[0] = m1[1]; j.out[0] = Qb;
    j.W[1] = WSLOT(5); j.bias[1] = m1[3]; j.out[1] = Kb;
    j.W[2] = WSLOT(6); j.bias[2] = m1[5]; j.out[2] = Vb;
    gemm_tf32_kernel<<<dim3(MTOT/GM, 3), 128, gemm_smem>>>(Xb, j, 0);
    attn_mma_kernel<<<agrid, 128, attn_smem>>>(Qb, Kb, Vb, Ob);
    j.W[0] = WSLOT(7); j.bias[0] = m1[7]; j.out[0] = Qb;   // SAB1 out -> Qb
    gemm_tf32_kernel<<<dim3(MTOT/GM, 1), 128, gemm_smem>>>(Ob, j, 2);

    // ---- PMA: K,V batched; qvec folded into pma_attn ----
    j.W[0] = WSLOT(8); j.bias[0] = m2[3]; j.out[0] = Kb;
    j.W[1] = WSLOT(9); j.bias[1] = m2[5]; j.out[1] = Vb;
    gemm_tf32_kernel<<<dim3(MTOT/GM, 2), 128, gemm_smem>>>(Qb, j, 0);
    pma_attn_kernel<<<dim3(HH, BB), 1024>>>(S, m2[0], m2[1], Kb, Vb, Pb);
    pma_final_kernel<<<BB, 256>>>(Pb, m2[6], m2[7], pW, pb, out);

    (void)in_sizes; (void)n_in; (void)out_size;
}